// round 4
// baseline (speedup 1.0000x reference)
#include <cuda_runtime.h>
#include <cstdint>
#include <cstdio>

// Batched greedy nearest-neighbor (B=64, N=1000).
//   distance (B,N,N) f32 | mask (B,N) bool (wire dtype sniffed) |
//   start (B,) i32 | pad scalar. Inputs identified by element count.
//   OUTPUT WRITTEN AS FLOAT32: [ pred (B,N) | pred_len (B,) ] -- the
//   exact-1.0 rel_err signature of rounds 0-3 says gpu-output ~ 0 under a
//   float32 comparison, i.e. our int32 writes were read as denormals.
//
// One warp per batch. Lane t owns elements {c*128 + t*4 + j : c<8, j<4}.
// Per step: 8x LDG.128 of current row -> 32 u64 keys (float_bits<<32 | idx)
// -> register min-tree + 5x shfl.bfly = exact argmin, first-index tie-break.

#ifndef GREEDY_N
#define GREEDY_N 1000
#endif

__global__ void __launch_bounds__(32, 1)
greedy_nn_kernel(const float* __restrict__ dist,
                 const void* __restrict__ mask_raw,
                 const int* __restrict__ start,
                 float* __restrict__ out,
                 int B, int out_size)
{
    constexpr int N = GREEDY_N;
    constexpr unsigned BIG_BITS = 0x49742400u;  // __float_as_uint(1.0e6f)
    const unsigned FULL = 0xffffffffu;

    const int b = blockIdx.x;
    const int t = threadIdx.x;

    // ---- sniff mask wire dtype from its first 512 bytes ----
    // any byte > 1            -> float32 (bytes of 1.0f)
    // nonzero byte at p%4!=0  -> uint8 bools
    // else                    -> int32 (little-endian 0/1)
    const uint8_t* mb = (const uint8_t*)mask_raw;
    bool weird = false, offnz = false;
#pragma unroll
    for (int i = 0; i < 16; ++i) {
        const int p = t * 16 + i;
        const uint8_t v = mb[p];
        if (v > 1) weird = true;
        if (v != 0 && (p & 3) != 0) offnz = true;
    }
    const int mode = __ballot_sync(FULL, weird) ? 2
                   : (__ballot_sync(FULL, offnz) ? 1 : 0);

    // ---- per-lane visited mask (32 owned elements) + unvisited count ----
    unsigned mbits = 0;
    int cnt = 0;
    const size_t moff = (size_t)b * N;
#pragma unroll
    for (int c = 0; c < 8; ++c) {
#pragma unroll
        for (int j = 0; j < 4; ++j) {
            const int idx = c * 128 + t * 4 + j;
            bool m = true;                     // out-of-range -> permanently masked
            if (idx < N) {
                if (mode == 0)      m = (((const int*)mask_raw)[moff + idx] != 0);
                else if (mode == 1) m = (((const uint8_t*)mask_raw)[moff + idx] != 0);
                else                m = (((const float*)mask_raw)[moff + idx] != 0.0f);
            }
            if (m) mbits |= 1u << (c * 4 + j);
            else   ++cnt;
        }
    }
    int rem = cnt;                             // pred_len for this batch
#pragma unroll
    for (int off = 16; off; off >>= 1)
        rem += __shfl_xor_sync(FULL, rem, off);

    const float* __restrict__ D = dist + (size_t)b * N * N;
    float* __restrict__ pred = out + (size_t)b * N;
    int point = start[b];
    if (point < 0 || point >= N) point = 0;    // defensive clamp

    // ---- greedy chain: exactly rem active steps ----
    for (int step = 0; step < rem; ++step) {
        const float* __restrict__ row = D + (size_t)point * N;

        float4 v[8];
#pragma unroll
        for (int c = 0; c < 8; ++c) {
            const int base = c * 128 + t * 4;
            if (base + 3 < N) v[c] = *reinterpret_cast<const float4*>(row + base);
            else              v[c] = make_float4(1e6f, 1e6f, 1e6f, 1e6f);
        }

        unsigned long long k[32];
#pragma unroll
        for (int c = 0; c < 8; ++c) {
            const int base = c * 128 + t * 4;
            const float* vp = &v[c].x;
#pragma unroll
            for (int j = 0; j < 4; ++j) {
                const unsigned fb = ((mbits >> (c * 4 + j)) & 1u)
                                        ? BIG_BITS : __float_as_uint(vp[j]);
                k[c * 4 + j] = ((unsigned long long)fb << 32)
                             | (unsigned)(base + j);
            }
        }
#pragma unroll
        for (int stride = 16; stride; stride >>= 1)
#pragma unroll
            for (int i = 0; i < 32; ++i)
                if (i < stride)
                    k[i] = (k[i] < k[i + stride]) ? k[i] : k[i + stride];

        unsigned long long best = k[0];
#pragma unroll
        for (int off = 16; off; off >>= 1) {
            unsigned long long o = __shfl_xor_sync(FULL, best, off);
            best = (best < o) ? best : o;
        }

        const int g = (int)(unsigned)best;     // argmin index
        if (t == 0) pred[step] = (float)g;     // FLOAT output

        if (t == ((g >> 2) & 31))              // owner lane marks visited
            mbits |= 1u << (((g >> 7) << 2) | (g & 3));
        point = g;
    }

    // ---- pad tail + pred_len (guarded by out_size), as floats ----
    for (int s = rem + t; s < N; s += 32) pred[s] = (float)N;  // pad_value == N
    if (t == 0 && (size_t)B * N + b < (size_t)out_size)
        out[(size_t)B * N + b] = (float)rem;
}

extern "C" void kernel_launch(void* const* d_in, const int* in_sizes, int n_in,
                              void* d_out, int out_size)
{
    // one-line ground truth for the next post-mortem, win or lose
    fprintf(stderr, "[greedy] n_in=%d sizes:", n_in);
    for (int i = 0; i < n_in && i < 8; ++i) fprintf(stderr, " %d", in_sizes[i]);
    fprintf(stderr, " out_size=%d\n", out_size);

    // identify inputs by element count, descending:
    // rank 0: distance (B*N*N)  rank 1: mask (B*N)  rank 2: start (B)  rank 3: pad
    int order[8];
    const int m = (n_in < 8) ? n_in : 8;
    for (int i = 0; i < m; ++i) order[i] = i;
    for (int i = 0; i < m; ++i)
        for (int j = i + 1; j < m; ++j)
            if (in_sizes[order[j]] > in_sizes[order[i]]) {
                int tmp = order[i]; order[i] = order[j]; order[j] = tmp;
            }

    const float* dist  = (const float*)d_in[order[0]];
    const void*  mask  = d_in[order[1]];
    const int*   start = (const int*)d_in[order[2]];
    float*       out   = (float*)d_out;

    // B: min over independent derivations -> 64 under any units/dtype combo
    const int N = GREEDY_N;
    long long cand[4];
    cand[0] = in_sizes[order[2]];                          // start count
    cand[1] = in_sizes[order[1]] / N;                      // mask / N
    cand[2] = in_sizes[order[0]] / ((long long)N * N);     // dist / N^2
    cand[3] = out_size / N;                                // out / N
    long long B = cand[0];
    for (int i = 1; i < 4; ++i)
        if (cand[i] >= 1 && cand[i] < B) B = cand[i];
    if (B < 1) B = 1;

    greedy_nn_kernel<<<(int)B, 32>>>(dist, mask, start, out, (int)B, out_size);
}

// round 5
// speedup vs baseline: 1.3287x; 1.3287x over previous
#include <cuda_runtime.h>
#include <cstdint>
#include <cstdio>

// Batched greedy nearest-neighbor (B=64, N=1000). Output float32:
//   [ pred (B,N) | pred_len (B,) ].
// One warp per batch; lane t owns elements {c*128 + t*4 + j : c<8, j<4}.
// R4 fix: two-pass (value-min, then first-matching-index-min) reduction with
// __reduce_min_sync. No u64 key array -> no register spills (R4 had regs=86
// and ~2000 cyc/step of local-memory traffic).
//   pass 1: u32 min over masked float bits (order == float order, values >= 0)
//   pass 2: min owned index with bits == gmin  ==> exact jnp.argmin tie-break.

#ifndef GREEDY_N
#define GREEDY_N 1000
#endif

__global__ void __launch_bounds__(32, 1)
greedy_nn_kernel(const float* __restrict__ dist,
                 const void* __restrict__ mask_raw,
                 const int* __restrict__ start,
                 float* __restrict__ out,
                 int B, int out_size)
{
    constexpr int N = GREEDY_N;
    constexpr unsigned BIG_BITS = 0x49742400u;  // __float_as_uint(1.0e6f)
    const unsigned FULL = 0xffffffffu;

    const int b = blockIdx.x;
    const int t = threadIdx.x;

    // ---- sniff mask wire dtype (first 512 bytes) ----
    const uint8_t* mbptr = (const uint8_t*)mask_raw;
    bool weird = false, offnz = false;
#pragma unroll
    for (int i = 0; i < 16; ++i) {
        const int p = t * 16 + i;
        const uint8_t v = mbptr[p];
        if (v > 1) weird = true;
        if (v != 0 && (p & 3) != 0) offnz = true;
    }
    const int mode = __ballot_sync(FULL, weird) ? 2
                   : (__ballot_sync(FULL, offnz) ? 1 : 0);

    // ---- per-lane visited mask (32 owned elements) + unvisited count ----
    unsigned mbits = 0;
    int cnt = 0;
    const size_t moff = (size_t)b * N;
#pragma unroll
    for (int c = 0; c < 8; ++c) {
#pragma unroll
        for (int j = 0; j < 4; ++j) {
            const int idx = c * 128 + t * 4 + j;
            bool m = true;                     // out-of-range -> permanently masked
            if (idx < N) {
                if (mode == 0)      m = (((const int*)mask_raw)[moff + idx] != 0);
                else if (mode == 1) m = (((const uint8_t*)mask_raw)[moff + idx] != 0);
                else                m = (((const float*)mask_raw)[moff + idx] != 0.0f);
            }
            if (m) mbits |= 1u << (c * 4 + j);
            else   ++cnt;
        }
    }
    int rem = cnt;                             // pred_len for this batch
#pragma unroll
    for (int off = 16; off; off >>= 1)
        rem += __shfl_xor_sync(FULL, rem, off);

    const float* __restrict__ D = dist + (size_t)b * N * N;
    float* __restrict__ pred = out + (size_t)b * N;
    int point = start[b];
    if (point < 0 || point >= N) point = 0;

    // ---- greedy chain: exactly rem active steps ----
    for (int step = 0; step < rem; ++step) {
        const float* __restrict__ row = D + (size_t)point * N;

        // issue all 8 row loads up front (coalesced LDG.128, MLP=8)
        float4 v[8];
#pragma unroll
        for (int c = 0; c < 8; ++c) {
            const int base = c * 128 + t * 4;
            if (base + 3 < N) v[c] = *reinterpret_cast<const float4*>(row + base);
            else              v[c] = make_float4(1e6f, 1e6f, 1e6f, 1e6f);
        }

        // masked value bits (u32 order == float order for non-negative values)
        unsigned ub[32];
#pragma unroll
        for (int c = 0; c < 8; ++c) {
            const float* vp = &v[c].x;
#pragma unroll
            for (int j = 0; j < 4; ++j)
                ub[c * 4 + j] = ((mbits >> (c * 4 + j)) & 1u)
                                    ? BIG_BITS : __float_as_uint(vp[j]);
        }

        // pass 1: global min value bits (tree + REDUX)
        unsigned mv[16];
#pragma unroll
        for (int i = 0; i < 16; ++i) mv[i] = umin(ub[i], ub[i + 16]);
#pragma unroll
        for (int s = 8; s; s >>= 1)
#pragma unroll
            for (int i = 0; i < 16; ++i)
                if (i < s) mv[i] = umin(mv[i], mv[i + s]);
        const unsigned gmin = __reduce_min_sync(FULL, mv[0]);

        // pass 2: min index whose bits == gmin (first occurrence == argmin)
        unsigned ic[16];
#pragma unroll
        for (int i = 0; i < 16; ++i) {
            const unsigned lo = (ub[i] == gmin)
                ? (unsigned)((i >> 2) * 128 + t * 4 + (i & 3)) : 0xffffffffu;
            const int i2 = i + 16;
            const unsigned hi = (ub[i2] == gmin)
                ? (unsigned)((i2 >> 2) * 128 + t * 4 + (i2 & 3)) : 0xffffffffu;
            ic[i] = umin(lo, hi);
        }
#pragma unroll
        for (int s = 8; s; s >>= 1)
#pragma unroll
            for (int i = 0; i < 16; ++i)
                if (i < s) ic[i] = umin(ic[i], ic[i + s]);
        const int g = (int)__reduce_min_sync(FULL, ic[0]);

        point = g;                              // feeds next iteration's loads
        if (t == ((g >> 2) & 31))               // owner lane marks visited
            mbits |= 1u << (((g >> 7) << 2) | (g & 3));
        if (t == 0) pred[step] = (float)g;      // fire-and-forget STG
    }

    // ---- pad tail + pred_len (guarded by out_size), as floats ----
    for (int s = rem + t; s < N; s += 32) pred[s] = (float)N;  // pad == N
    if (t == 0 && (size_t)B * N + b < (size_t)out_size)
        out[(size_t)B * N + b] = (float)rem;
}

extern "C" void kernel_launch(void* const* d_in, const int* in_sizes, int n_in,
                              void* d_out, int out_size)
{
    fprintf(stderr, "[greedy] n_in=%d sizes:", n_in);
    for (int i = 0; i < n_in && i < 8; ++i) fprintf(stderr, " %d", in_sizes[i]);
    fprintf(stderr, " out_size=%d\n", out_size);

    // identify inputs by element count, descending
    int order[8];
    const int m = (n_in < 8) ? n_in : 8;
    for (int i = 0; i < m; ++i) order[i] = i;
    for (int i = 0; i < m; ++i)
        for (int j = i + 1; j < m; ++j)
            if (in_sizes[order[j]] > in_sizes[order[i]]) {
                int tmp = order[i]; order[i] = order[j]; order[j] = tmp;
            }

    const float* dist  = (const float*)d_in[order[0]];
    const void*  mask  = d_in[order[1]];
    const int*   start = (const int*)d_in[order[2]];
    float*       out   = (float*)d_out;

    const int N = GREEDY_N;
    long long cand[4];
    cand[0] = in_sizes[order[2]];
    cand[1] = in_sizes[order[1]] / N;
    cand[2] = in_sizes[order[0]] / ((long long)N * N);
    cand[3] = out_size / N;
    long long B = cand[0];
    for (int i = 1; i < 4; ++i)
        if (cand[i] >= 1 && cand[i] < B) B = cand[i];
    if (B < 1) B = 1;

    greedy_nn_kernel<<<(int)B, 32>>>(dist, mask, start, out, (int)B, out_size);
}

// round 7
// speedup vs baseline: 3.1228x; 2.3504x over previous
#include <cuda_runtime.h>
#include <cstdint>
#include <cstdio>

// Batched greedy nearest-neighbor (B<=64, N=1000). Output float32:
//   [ pred (B,N) | pred_len (B,) ].
//
// R6 design: per-row top-24 candidate lists (exact (bits,idx) order) are
// precomputed by a throughput kernel into a 3MB __device__ table; the chain
// kernel stages its batch's 48KB slice in SMEM and resolves each greedy step
// with LDS + shfl-bitset + ballot (~150cyc) instead of a 4KB DRAM row fetch
// (~2000cyc). If all 24 candidates are visited (expected ~40x per batch),
// an exact full-row fallback scan runs. Semantics identical to jnp.argmin
// with first-index tie-break in every case.

#define GN   1000
#define GK   24
#define MAXB 64

__device__ __align__(16) unsigned short g_cand[(size_t)MAXB * GN * GK]; // 3MB

// --------------------------------------------------------------------------
// per-lane exact min key over the lane's 32 owned elements, excluding `sel`
// ownership: lane t owns idx = c*128 + 4t + j  (c<8, j<4), kb[e], e = c*4+j
__device__ __forceinline__ unsigned long long
extract_min(const unsigned* kb, unsigned sel, int t)
{
    unsigned long long best = ~0ull;
#pragma unroll
    for (int e = 0; e < 32; ++e) {
        const unsigned idx = (unsigned)((e >> 2) * 128 + 4 * t + (e & 3));
        unsigned long long k = ((unsigned long long)kb[e] << 32) | idx;
        if ((sel >> e) & 1u) k = ~0ull;
        best = (k < best) ? k : best;
    }
    return best;
}

// ---- preprocess: one warp per row -> 24 smallest indices, sorted ----------
__global__ void topk_kernel(const float* __restrict__ dist, int rows)
{
    const int w = blockIdx.x * (blockDim.x >> 5) + (threadIdx.x >> 5);
    if (w >= rows) return;
    const int t = threadIdx.x & 31;
    const unsigned FULL = 0xffffffffu;
    const float* __restrict__ row = dist + (size_t)w * GN;

    // load + key bits (invalid tail -> 0xffffffff, can never win)
    unsigned kb[32];
#pragma unroll
    for (int c = 0; c < 8; ++c) {
        const int base = c * 128 + 4 * t;
        float4 v = make_float4(0, 0, 0, 0);
        if (base + 3 < GN) v = *reinterpret_cast<const float4*>(row + base);
        const float* vp = &v.x;
#pragma unroll
        for (int j = 0; j < 4; ++j)
            kb[c * 4 + j] = (base + 3 < GN) ? __float_as_uint(vp[j]) : 0xffffffffu;
    }

    // per-lane sorted top-4 (extraction)
    unsigned long long top[4];
    {
        unsigned pm = 0;
#pragma unroll
        for (int p = 0; p < 4; ++p) {
            const unsigned long long k = extract_min(kb, pm, t);
            top[p] = k;
            const unsigned idx = (unsigned)k;
            pm |= 1u << (((idx >> 7) << 2) | (idx & 3));
        }
    }

    // 24 tournament rounds; winners emerge in exact (bits,idx) order
    unsigned sel = 0;
    int ptr = 0;
    unsigned long long cand = top[0];
    unsigned short* crow = g_cand + (size_t)w * GK;
    for (int rnd = 0; rnd < GK; ++rnd) {
        const unsigned hi   = (unsigned)(cand >> 32);
        const unsigned ghi  = __reduce_min_sync(FULL, hi);
        const unsigned mylo = (hi == ghi) ? (unsigned)cand : 0xffffffffu;
        const unsigned gidx = __reduce_min_sync(FULL, mylo);
        if (t == 0) crow[rnd] = (unsigned short)gidx;
        if (hi == ghi && (unsigned)cand == gidx) {       // unique owner
            sel |= 1u << (((gidx >> 7) << 2) | (gidx & 3));
            ++ptr;
            cand = (ptr < 4) ? top[ptr] : extract_min(kb, sel, t);
        }
    }
}

// ---- exact fallback: full-row masked argmin (lane t owns [32t, 32t+32)) ---
__device__ __forceinline__ int
fb_scan(const float* __restrict__ row, unsigned vis, int t)
{
    const unsigned FULL = 0xffffffffu;
    unsigned long long best = ~0ull;
#pragma unroll
    for (int j = 0; j < 8; ++j) {
        const int base = 32 * t + 4 * j;
        if (base + 3 < GN) {
            const float4 v = *reinterpret_cast<const float4*>(row + base);
            const float* vp = &v.x;
#pragma unroll
            for (int q = 0; q < 4; ++q) {
                const int e = 4 * j + q;
                const unsigned fb = ((vis >> e) & 1u) ? 0xffffffffu
                                                      : __float_as_uint(vp[q]);
                const unsigned long long k =
                    ((unsigned long long)fb << 32) | (unsigned)(base + q);
                best = (k < best) ? k : best;
            }
        }
    }
    const unsigned hi   = (unsigned)(best >> 32);
    const unsigned ghi  = __reduce_min_sync(FULL, hi);
    const unsigned mylo = (hi == ghi) ? (unsigned)best : 0xffffffffu;
    return (int)__reduce_min_sync(FULL, mylo);
}

// ---- chain: one warp per batch, candidates in SMEM ------------------------
__global__ void __launch_bounds__(32, 1)
chain_kernel(const float* __restrict__ dist,
             const void* __restrict__ mask_raw,
             const int* __restrict__ start,
             float* __restrict__ out,
             int B, int out_size)
{
    __shared__ __align__(16) unsigned short s_cand[GN * GK];   // 48000 B
    const int b = blockIdx.x;
    const int t = threadIdx.x;
    const unsigned FULL = 0xffffffffu;

    // stage this batch's candidate table (48KB, uint4 copies)
    {
        const uint4* src = reinterpret_cast<const uint4*>(
            g_cand + (size_t)b * GN * GK);
        uint4* dst = reinterpret_cast<uint4*>(s_cand);
        for (int i = t; i < (GN * GK * 2) / 16; i += 32) dst[i] = src[i];
    }

    // sniff mask wire dtype (first 512 bytes)
    const uint8_t* mbp = (const uint8_t*)mask_raw;
    bool weird = false, offnz = false;
#pragma unroll
    for (int i = 0; i < 16; ++i) {
        const int p = t * 16 + i;
        const uint8_t v = mbp[p];
        if (v > 1) weird = true;
        if (v != 0 && (p & 3) != 0) offnz = true;
    }
    const int mode = __ballot_sync(FULL, weird) ? 2
                   : (__ballot_sync(FULL, offnz) ? 1 : 0);

    // visited bitset: word t covers idx [32t, 32t+32); OOR bits set
    unsigned visited = 0;
    const size_t moff = (size_t)b * GN;
#pragma unroll
    for (int j = 0; j < 32; ++j) {
        const int idx = 32 * t + j;
        bool m = true;
        if (idx < GN) {
            if (mode == 0)      m = (((const int*)mask_raw)[moff + idx] != 0);
            else if (mode == 1) m = (((const uint8_t*)mask_raw)[moff + idx] != 0);
            else                m = (((const float*)mask_raw)[moff + idx] != 0.0f);
        }
        if (m) visited |= 1u << j;
    }
    const int rem = __reduce_add_sync(FULL, __popc(~visited));  // pred_len

    __syncwarp();                                   // s_cand ready

    const float* __restrict__ D = dist + (size_t)b * GN * GN;
    float* __restrict__ pred = out + (size_t)b * GN;
    int point = start[b];
    if (point < 0 || point >= GN) point = 0;

    for (int step = 0; step < rem; ++step) {
        // probe the 24 sorted candidates of the current row
        unsigned cc = 0;
        if (t < GK) cc = (unsigned)s_cand[point * GK + t];
        const unsigned vw = __shfl_sync(FULL, visited, (cc >> 5) & 31);
        const bool unvis = (t < GK) && !((vw >> (cc & 31)) & 1u);
        const unsigned bal = __ballot_sync(FULL, unvis);

        int g;
        if (bal) {                                   // lowest lane = argmin
            g = __shfl_sync(FULL, cc, __ffs(bal) - 1);
        } else {                                     // exact full-row scan
            g = fb_scan(D + (size_t)point * GN, visited, t);
        }

        if (t == (g >> 5)) visited |= 1u << (g & 31);
        if (t == 0) pred[step] = (float)g;
        point = g;
    }

    // pad tail + pred_len (guarded), as floats
    for (int s = rem + t; s < GN; s += 32) pred[s] = (float)GN;
    if (t == 0 && (size_t)B * GN + b < (size_t)out_size)
        out[(size_t)B * GN + b] = (float)rem;
}

extern "C" void kernel_launch(void* const* d_in, const int* in_sizes, int n_in,
                              void* d_out, int out_size)
{
    fprintf(stderr, "[greedy] n_in=%d sizes:", n_in);
    for (int i = 0; i < n_in && i < 8; ++i) fprintf(stderr, " %d", in_sizes[i]);
    fprintf(stderr, " out_size=%d\n", out_size);

    // identify inputs by element count, descending
    int order[8];
    const int m = (n_in < 8) ? n_in : 8;
    for (int i = 0; i < m; ++i) order[i] = i;
    for (int i = 0; i < m; ++i)
        for (int j = i + 1; j < m; ++j)
            if (in_sizes[order[j]] > in_sizes[order[i]]) {
                int tmp = order[i]; order[i] = order[j]; order[j] = tmp;
            }

    const float* dist  = (const float*)d_in[order[0]];
    const void*  mask  = d_in[order[1]];
    const int*   start = (const int*)d_in[order[2]];
    float*       out   = (float*)d_out;

    long long cand[4];
    cand[0] = in_sizes[order[2]];
    cand[1] = in_sizes[order[1]] / GN;
    cand[2] = in_sizes[order[0]] / ((long long)GN * GN);
    cand[3] = out_size / GN;
    long long B = cand[0];
    for (int i = 1; i < 4; ++i)
        if (cand[i] >= 1 && cand[i] < B) B = cand[i];
    if (B < 1) B = 1;
    if (B > MAXB) B = MAXB;

    const int rows = (int)B * GN;
    const int wpb  = 8;                       // 8 warps (256 threads) per CTA
    topk_kernel<<<(rows + wpb - 1) / wpb, wpb * 32>>>(dist, rows);
    chain_kernel<<<(int)B, 32>>>(dist, mask, start, out, (int)B, out_size);
}

// round 11
// speedup vs baseline: 3.7477x; 1.2001x over previous
#include <cuda_runtime.h>
#include <cstdint>
#include <cstdio>

// Batched greedy nearest-neighbor (B<=64, N=1000). Output float32:
//   [ pred (B,N) | pred_len (B,) ].
// R8: topk rewritten as threshold-compaction selection (exact), chain loop
// unrolled. Per-row top-24 candidate indices (exact (bits,idx) order) in a
// 3MB __device__ table; chain kernel probes them from SMEM per step, with an
// exact full-row fallback when all 24 are visited (~40x/batch).

#define GN   1000
#define GK   24
#define MAXB 64

__device__ __align__(16) unsigned short g_cand[(size_t)MAXB * GN * GK]; // 3MB

// --------------------------------------------------------------------------
// slow-path helper: per-lane exact min key over 32 owned elems minus `sel`
// ownership: lane t owns idx = c*128 + 4t + j (c<8, j<4); kb[e], e = c*4+j
__device__ __forceinline__ unsigned long long
extract_min(const unsigned* kb, unsigned sel, int t)
{
    unsigned long long best = ~0ull;
#pragma unroll
    for (int e = 0; e < 32; ++e) {
        const unsigned idx = (unsigned)((e >> 2) * 128 + 4 * t + (e & 3));
        unsigned long long k = ((unsigned long long)kb[e] << 32) | idx;
        if ((sel >> e) & 1u) k = ~0ull;
        best = (k < best) ? k : best;
    }
    return best;
}

// u64 compare-exchange (ascending)
__device__ __forceinline__ void cswap(unsigned long long& a, unsigned long long& b)
{
    const unsigned long long lo = (a < b) ? a : b;
    b = (a < b) ? b : a;
    a = lo;
}

// ---- preprocess: one warp per row -> 24 smallest indices, sorted exactly ---
__global__ void __launch_bounds__(256)
topk_kernel(const float* __restrict__ dist, int rows)
{
    __shared__ unsigned long long comp[8][128];          // 8KB / CTA
    const int wi = threadIdx.x >> 5;
    const int w  = blockIdx.x * 8 + wi;
    if (w >= rows) return;
    const int t = threadIdx.x & 31;
    const unsigned FULL = 0xffffffffu;
    constexpr float T_F = 0.0625f;                        // E[cnt]=62.5, sd=7.7

    const float* __restrict__ row = dist + (size_t)w * GN;
    unsigned short* __restrict__ crow = g_cand + (size_t)w * GK;

    // load 32 owned values (tail -> 1e6, never below threshold)
    float4 v[8];
#pragma unroll
    for (int c = 0; c < 8; ++c) {
        const int base = c * 128 + 4 * t;
        if (base + 3 < GN) v[c] = *reinterpret_cast<const float4*>(row + base);
        else               v[c] = make_float4(1e6f, 1e6f, 1e6f, 1e6f);
    }

    // per-lane count below threshold
    int cnt = 0;
#pragma unroll
    for (int c = 0; c < 8; ++c) {
        const float* vp = &v[c].x;
#pragma unroll
        for (int j = 0; j < 4; ++j) cnt += (vp[j] < T_F) ? 1 : 0;
    }
    const int total = __reduce_add_sync(FULL, (unsigned)cnt);

    if (total >= GK && total <= 128) {
        // ---- fast path: compact keys < T, select 24 smallest exactly ----
        unsigned scan = (unsigned)cnt;                    // inclusive prefix
#pragma unroll
        for (int off = 1; off < 32; off <<= 1) {
            const unsigned n = __shfl_up_sync(FULL, scan, off);
            if (t >= off) scan += n;
        }
        unsigned ptr = scan - (unsigned)cnt;              // exclusive
        unsigned long long* cbuf = comp[wi];
#pragma unroll
        for (int c = 0; c < 8; ++c) {
            const int base = c * 128 + 4 * t;
            const float* vp = &v[c].x;
#pragma unroll
            for (int j = 0; j < 4; ++j) {
                if (vp[j] < T_F) {
                    cbuf[ptr++] = ((unsigned long long)__float_as_uint(vp[j]) << 32)
                                | (unsigned)(base + j);
                }
            }
        }
        __syncwarp();

        // each lane owns entries {t, t+32, t+64, t+96}; sort its <=4
        unsigned long long e0 = (t < total)      ? cbuf[t]      : ~0ull;
        unsigned long long e1 = (t + 32 < total) ? cbuf[t + 32] : ~0ull;
        unsigned long long e2 = (t + 64 < total) ? cbuf[t + 64] : ~0ull;
        unsigned long long e3 = (t + 96 < total) ? cbuf[t + 96] : ~0ull;
        cswap(e0, e1); cswap(e2, e3); cswap(e0, e2); cswap(e1, e3); cswap(e1, e2);

        unsigned long long cand = e0;
#pragma unroll
        for (int rnd = 0; rnd < GK; ++rnd) {
            const unsigned hi   = (unsigned)(cand >> 32);
            const unsigned ghi  = __reduce_min_sync(FULL, hi);
            const unsigned mylo = (hi == ghi) ? (unsigned)cand : 0xffffffffu;
            const unsigned glo  = __reduce_min_sync(FULL, mylo);
            if (t == 0) crow[rnd] = (unsigned short)glo;
            if (hi == ghi && (unsigned)cand == glo) {     // unique winner
                e0 = e1; e1 = e2; e2 = e3; e3 = ~0ull;    // advance supply
                cand = e0;
            }
        }
    } else {
        // ---- rare exact retry (~2e-7/row): original tournament ----
        unsigned kb[32];
#pragma unroll
        for (int c = 0; c < 8; ++c) {
            const int base = c * 128 + 4 * t;
            const float* vp = &v[c].x;
#pragma unroll
            for (int j = 0; j < 4; ++j)
                kb[c * 4 + j] = (base + 3 < GN) ? __float_as_uint(vp[j])
                                                : 0xffffffffu;
        }
        unsigned long long top[4];
        unsigned pm = 0;
#pragma unroll
        for (int p = 0; p < 4; ++p) {
            top[p] = extract_min(kb, pm, t);
            const unsigned idx = (unsigned)top[p];
            pm |= 1u << (((idx >> 7) << 2) | (idx & 3));
        }
        unsigned sel = 0;
        int ptr = 0;
        unsigned long long cand = top[0];
        for (int rnd = 0; rnd < GK; ++rnd) {
            const unsigned hi   = (unsigned)(cand >> 32);
            const unsigned ghi  = __reduce_min_sync(FULL, hi);
            const unsigned mylo = (hi == ghi) ? (unsigned)cand : 0xffffffffu;
            const unsigned gidx = __reduce_min_sync(FULL, mylo);
            if (t == 0) crow[rnd] = (unsigned short)gidx;
            if (hi == ghi && (unsigned)cand == gidx) {
                sel |= 1u << (((gidx >> 7) << 2) | (gidx & 3));
                ++ptr;
                cand = (ptr < 4) ? top[ptr] : extract_min(kb, sel, t);
            }
        }
    }
}

// ---- exact fallback: full-row masked argmin (lane t owns [32t, 32t+32)) ---
__device__ __forceinline__ int
fb_scan(const float* __restrict__ row, unsigned vis, int t)
{
    const unsigned FULL = 0xffffffffu;
    unsigned long long best = ~0ull;
#pragma unroll
    for (int j = 0; j < 8; ++j) {
        const int base = 32 * t + 4 * j;
        if (base + 3 < GN) {
            const float4 v = *reinterpret_cast<const float4*>(row + base);
            const float* vp = &v.x;
#pragma unroll
            for (int q = 0; q < 4; ++q) {
                const int e = 4 * j + q;
                const unsigned fb = ((vis >> e) & 1u) ? 0xffffffffu
                                                      : __float_as_uint(vp[q]);
                const unsigned long long k =
                    ((unsigned long long)fb << 32) | (unsigned)(base + q);
                best = (k < best) ? k : best;
            }
        }
    }
    const unsigned hi   = (unsigned)(best >> 32);
    const unsigned ghi  = __reduce_min_sync(FULL, hi);
    const unsigned mylo = (hi == ghi) ? (unsigned)best : 0xffffffffu;
    return (int)__reduce_min_sync(FULL, mylo);
}

// ---- chain: one warp per batch, candidates in SMEM ------------------------
__global__ void __launch_bounds__(32, 1)
chain_kernel(const float* __restrict__ dist,
             const void* __restrict__ mask_raw,
             const int* __restrict__ start,
             float* __restrict__ out,
             int B, int out_size)
{
    __shared__ __align__(16) unsigned short s_cand[GN * GK];   // 48000 B
    const int b = blockIdx.x;
    const int t = threadIdx.x;
    const unsigned FULL = 0xffffffffu;

    // stage this batch's candidate table (48KB, uint4 copies)
    {
        const uint4* src = reinterpret_cast<const uint4*>(
            g_cand + (size_t)b * GN * GK);
        uint4* dst = reinterpret_cast<uint4*>(s_cand);
        for (int i = t; i < (GN * GK * 2) / 16; i += 32) dst[i] = src[i];
    }

    // sniff mask wire dtype (first 512 bytes)
    const uint8_t* mbp = (const uint8_t*)mask_raw;
    bool weird = false, offnz = false;
#pragma unroll
    for (int i = 0; i < 16; ++i) {
        const int p = t * 16 + i;
        const uint8_t v = mbp[p];
        if (v > 1) weird = true;
        if (v != 0 && (p & 3) != 0) offnz = true;
    }
    const int mode = __ballot_sync(FULL, weird) ? 2
                   : (__ballot_sync(FULL, offnz) ? 1 : 0);

    // visited bitset: word t covers idx [32t, 32t+32); OOR bits set
    unsigned visited = 0;
    const size_t moff = (size_t)b * GN;
#pragma unroll
    for (int j = 0; j < 32; ++j) {
        const int idx = 32 * t + j;
        bool m = true;
        if (idx < GN) {
            if (mode == 0)      m = (((const int*)mask_raw)[moff + idx] != 0);
            else if (mode == 1) m = (((const uint8_t*)mask_raw)[moff + idx] != 0);
            else                m = (((const float*)mask_raw)[moff + idx] != 0.0f);
        }
        if (m) visited |= 1u << j;
    }
    const int rem = __reduce_add_sync(FULL, __popc(~visited));  // pred_len

    __syncwarp();                                   // s_cand ready

    const float* __restrict__ D = dist + (size_t)b * GN * GN;
    float* __restrict__ pred = out + (size_t)b * GN;
    int point = start[b];
    if (point < 0 || point >= GN) point = 0;

    // per-lane byte offset into a candidate row, hoisted out of the loop
    const unsigned short* __restrict__ cl = s_cand + t;

#pragma unroll 2
    for (int step = 0; step < rem; ++step) {
        // probe the 24 sorted candidates of the current row
        unsigned cc = 0;
        if (t < GK) cc = (unsigned)cl[point * GK];
        const unsigned vw = __shfl_sync(FULL, visited, (cc >> 5) & 31);
        const bool unvis = (t < GK) && !((vw >> (cc & 31)) & 1u);
        const unsigned bal = __ballot_sync(FULL, unvis);

        int g;
        if (bal) {                                   // lowest lane = argmin
            g = __shfl_sync(FULL, cc, __ffs(bal) - 1);
        } else {                                     // exact full-row scan
            g = fb_scan(D + (size_t)point * GN, visited, t);
        }

        if (t == (g >> 5)) visited |= 1u << (g & 31);
        if (t == 0) pred[step] = (float)g;
        point = g;
    }

    // pad tail + pred_len (guarded), as floats
    for (int s = rem + t; s < GN; s += 32) pred[s] = (float)GN;
    if (t == 0 && (size_t)B * GN + b < (size_t)out_size)
        out[(size_t)B * GN + b] = (float)rem;
}

extern "C" void kernel_launch(void* const* d_in, const int* in_sizes, int n_in,
                              void* d_out, int out_size)
{
    fprintf(stderr, "[greedy] n_in=%d sizes:", n_in);
    for (int i = 0; i < n_in && i < 8; ++i) fprintf(stderr, " %d", in_sizes[i]);
    fprintf(stderr, " out_size=%d\n", out_size);

    // identify inputs by element count, descending
    int order[8];
    const int m = (n_in < 8) ? n_in : 8;
    for (int i = 0; i < m; ++i) order[i] = i;
    for (int i = 0; i < m; ++i)
        for (int j = i + 1; j < m; ++j)
            if (in_sizes[order[j]] > in_sizes[order[i]]) {
                int tmp = order[i]; order[i] = order[j]; order[j] = tmp;
            }

    const float* dist  = (const float*)d_in[order[0]];
    const void*  mask  = d_in[order[1]];
    const int*   start = (const int*)d_in[order[2]];
    float*       out   = (float*)d_out;

    long long cand[4];
    cand[0] = in_sizes[order[2]];
    cand[1] = in_sizes[order[1]] / GN;
    cand[2] = in_sizes[order[0]] / ((long long)GN * GN);
    cand[3] = out_size / GN;
    long long B = cand[0];
    for (int i = 1; i < 4; ++i)
        if (cand[i] >= 1 && cand[i] < B) B = cand[i];
    if (B < 1) B = 1;
    if (B > MAXB) B = MAXB;

    const int rows = (int)B * GN;
    topk_kernel<<<(rows + 7) / 8, 256>>>(dist, rows);
    chain_kernel<<<(int)B, 32>>>(dist, mask, start, out, (int)B, out_size);
}